// round 15
// baseline (speedup 1.0000x reference)
#include <cuda_runtime.h>
#include <math.h>
#include <stdint.h>

#define N_NODES 50000
#define FDIM    160
#define NMAX    50020   // N + S_EXTRA(20); divisible by 4
#define NEDGE   500000
#define DKDIM   64
#define NGRAPH  7
#define OFFSTR  (NMAX + 4)   // per-graph offset stride, 16B multiple

// ---------------- static device scratch (no runtime allocation) ----------------
__device__ float g_X0 [NMAX * FDIM];
__device__ float g_Hb [5][NMAX * FDIM];   // per-job GEMM outputs
__device__ float g_T3 [NMAX * FDIM];
__device__ float g_T5 [NMAX * FDIM];
__device__ float g_A1 [NMAX * FDIM];
__device__ float g_A2 [NMAX * FDIM];
__device__ float g_A3 [NMAX * FDIM];
__device__ float g_A4 [NMAX * FDIM];
__device__ float g_Ady[NMAX * FDIM];
__device__ float g_U  [NMAX * FDIM];
__device__ float g_M1 [FDIM * FDIM];
__device__ float g_v1 [FDIM];
__device__ float g_elB[5][NMAX];
__device__ float g_erB[5][NMAX];
__device__ __align__(16) int g_cntB [NGRAPH * NMAX];
__device__ __align__(16) int g_curB [NGRAPH * NMAX];
__device__ __align__(16) int g_offB [NGRAPH * OFFSTR];
__device__ int   g_ssrcB[NGRAPH * NEDGE];

struct EdgePtrs { const int* src[NGRAPH]; const int* dst[NGRAPH]; };

struct GemmJob {
    const float* A; const float* W; const float* bias;
    const float* al; const float* ar;
    float* C; float* el; float* er; int n;
};
struct GemmBatch { GemmJob j[5]; };

struct GatherJob {
    const float* b; const float* H; float* dest;
    const float* el; const float* er;
    const int* off; const int* ssrc; int n;
};
struct GatherBatch { GatherJob j[5]; };

// ---------------- helpers ----------------
__device__ __forceinline__ float warp_sum(float v) {
    #pragma unroll
    for (int o = 16; o > 0; o >>= 1) v += __shfl_xor_sync(0xffffffffu, v, o);
    return v;
}
__device__ __forceinline__ float warp_max(float v) {
    #pragma unroll
    for (int o = 16; o > 0; o >>= 1) v = fmaxf(v, __shfl_xor_sync(0xffffffffu, v, o));
    return v;
}

__device__ __forceinline__ void tf32_split(float x, uint32_t& hi, uint32_t& lo) {
    asm("cvt.rna.tf32.f32 %0, %1;" : "=r"(hi) : "f"(x));
    float r = x - __uint_as_float(hi);
    asm("cvt.rna.tf32.f32 %0, %1;" : "=r"(lo) : "f"(r));
}

__device__ __forceinline__ void mma8(float acc[4], const uint32_t a[4],
                                     uint32_t b0, uint32_t b1) {
    asm volatile(
        "mma.sync.aligned.m16n8k8.row.col.f32.tf32.tf32.f32 "
        "{%0,%1,%2,%3}, {%4,%5,%6,%7}, {%8,%9}, {%0,%1,%2,%3};"
        : "+f"(acc[0]), "+f"(acc[1]), "+f"(acc[2]), "+f"(acc[3])
        : "r"(a[0]), "r"(a[1]), "r"(a[2]), "r"(a[3]), "r"(b0), "r"(b1));
}

// ---------------- batched CSR build ----------------
__global__ void batched_zero_kernel() {
    int i = blockIdx.x * blockDim.x + threadIdx.x;
    int n4 = NGRAPH * NMAX / 4;
    if (i < n4) {
        ((int4*)g_cntB)[i] = make_int4(0, 0, 0, 0);
        ((int4*)g_curB)[i] = make_int4(0, 0, 0, 0);
    }
}

__global__ void batched_hist_kernel(EdgePtrs ep) {
    int i = blockIdx.x * blockDim.x + threadIdx.x;
    if (i >= NGRAPH * NEDGE) return;
    int g = i / NEDGE, j = i - g * NEDGE;
    atomicAdd(&g_cntB[g * NMAX + ep.dst[g][j]], 1);
}

__global__ void batched_scan_kernel() {
    const int b = blockIdx.x;
    const int t = threadIdx.x;
    const int* cnt = g_cntB + b * NMAX;
    int* off = g_offB + b * OFFSTR;
    const int n4 = NMAX / 4;
    const int C4 = (n4 + 1023) / 1024;
    __shared__ int part[1024];

    int s = 0;
    for (int i = 0; i < C4; i++) {
        int idx = t * C4 + i;
        if (idx < n4) {
            int4 v = ((const int4*)cnt)[idx];
            s += v.x + v.y + v.z + v.w;
        }
    }
    part[t] = s;
    __syncthreads();
    for (int o = 1; o < 1024; o <<= 1) {
        int u = (t >= o) ? part[t - o] : 0;
        __syncthreads();
        part[t] += u;
        __syncthreads();
    }
    int run = part[t] - s;

    for (int i = 0; i < C4; i++) {
        int idx = t * C4 + i;
        if (idx < n4) {
            int4 v = ((const int4*)cnt)[idx];
            int4 o;
            o.x = run; run += v.x;
            o.y = run; run += v.y;
            o.z = run; run += v.z;
            o.w = run; run += v.w;
            ((int4*)off)[idx] = o;
        }
    }
    if (t == 1023) off[NMAX] = run;
}

__global__ void batched_fill_kernel(EdgePtrs ep) {
    int i = blockIdx.x * blockDim.x + threadIdx.x;
    if (i >= NGRAPH * NEDGE) return;
    int g = i / NEDGE, j = i - g * NEDGE;
    int d = ep.dst[g][j];
    int slot = g_offB[g * OFFSTR + d] + atomicAdd(&g_curB[g * NMAX + d], 1);
    g_ssrcB[g * NEDGE + slot] = ep.src[g][j];
}

// ---------------- batched TF32 tensor-core GEMM (3-term split) ----------------
// 512 threads = 16 warps (4m x 4n); tile 64 x 160; each warp 16 rows x 40 cols.
__global__ __launch_bounds__(512, 2)
void gemm_tc_batched(GemmBatch gb) {
    const GemmJob jb = gb.j[blockIdx.y];
    const int n = jb.n;
    const int row0 = blockIdx.x * 64;
    if (row0 >= n) return;   // uniform per block

    __shared__ uint32_t AsHi[64][20];
    __shared__ uint32_t AsLo[64][20];
    __shared__ uint32_t BsHi[16][168];
    __shared__ uint32_t BsLo[16][168];
    __shared__ float    s_al[FDIM], s_ar[FDIM];
    __shared__ float    s_elr[4][2][64];    // [wn][el/er][row]

    const float* __restrict__ A = jb.A;
    const float* __restrict__ B = jb.W;

    const int tid  = threadIdx.x;
    const int wid  = tid >> 5;
    const int lane = tid & 31;
    const int wm   = wid & 3;               // 4 m-groups of 16 rows
    const int wn   = wid >> 2;              // 4 n-groups of 40 cols
    const int m0   = wm * 16;
    const int c0w  = wn * 40;
    const int rl   = lane >> 2;
    const int kq   = lane & 3;

    if (jb.al) {
        for (int i = tid; i < FDIM; i += 512) { s_al[i] = jb.al[i]; s_ar[i] = jb.ar[i]; }
    }

    float acc[5][4];
    #pragma unroll
    for (int s = 0; s < 5; s++)
        #pragma unroll
        for (int q = 0; q < 4; q++) acc[s][q] = 0.0f;

    for (int k0 = 0; k0 < FDIM; k0 += 16) {
        // stage A 64x16 (float2 per thread), pre-split tf32 hi/lo
        {
            int m = tid >> 3, kc = (tid & 7) * 2;
            int r = row0 + m;
            float2 v = (r < n) ? *(const float2*)(A + (size_t)r * FDIM + k0 + kc)
                               : make_float2(0.f, 0.f);
            uint32_t h0, l0, h1, l1;
            tf32_split(v.x, h0, l0); tf32_split(v.y, h1, l1);
            AsHi[m][kc] = h0; AsHi[m][kc + 1] = h1;
            AsLo[m][kc] = l0; AsLo[m][kc + 1] = l1;
        }
        // stage B 16x160 (640 float4s over 512 threads), pre-split tf32 hi/lo
        for (int i = tid; i < 16 * 40; i += 512) {
            int k = i / 40, c4 = i - k * 40;
            float4 v = *(const float4*)(B + (size_t)(k0 + k) * FDIM + c4 * 4);
            uint32_t h0, l0, h1, l1, h2, l2, h3, l3;
            tf32_split(v.x, h0, l0); tf32_split(v.y, h1, l1);
            tf32_split(v.z, h2, l2); tf32_split(v.w, h3, l3);
            uint32_t* ph = &BsHi[k][c4 * 4];
            uint32_t* pl = &BsLo[k][c4 * 4];
            ph[0] = h0; ph[1] = h1; ph[2] = h2; ph[3] = h3;
            pl[0] = l0; pl[1] = l1; pl[2] = l2; pl[3] = l3;
        }
        __syncthreads();

        #pragma unroll
        for (int ks = 0; ks < 2; ks++) {
            const int kk = ks * 8;
            uint32_t ah[4], alo[4];
            ah[0]  = AsHi[m0 + rl][kk + kq];
            ah[1]  = AsHi[m0 + rl + 8][kk + kq];
            ah[2]  = AsHi[m0 + rl][kk + kq + 4];
            ah[3]  = AsHi[m0 + rl + 8][kk + kq + 4];
            alo[0] = AsLo[m0 + rl][kk + kq];
            alo[1] = AsLo[m0 + rl + 8][kk + kq];
            alo[2] = AsLo[m0 + rl][kk + kq + 4];
            alo[3] = AsLo[m0 + rl + 8][kk + kq + 4];
            #pragma unroll
            for (int s = 0; s < 5; s++) {
                const int cc = c0w + s * 8 + rl;
                uint32_t bh0 = BsHi[kk + kq][cc];
                uint32_t bh1 = BsHi[kk + kq + 4][cc];
                uint32_t bl0 = BsLo[kk + kq][cc];
                uint32_t bl1 = BsLo[kk + kq + 4][cc];
                mma8(acc[s], ah,  bh0, bh1);
                mma8(acc[s], alo, bh0, bh1);
                mma8(acc[s], ah,  bl0, bl1);
            }
        }
        __syncthreads();
    }

    const int cq2 = kq * 2;
    {
        int ra = row0 + m0 + rl;
        int rb = ra + 8;
        #pragma unroll
        for (int s = 0; s < 5; s++) {
            int c = c0w + s * 8 + cq2;
            float b0v = jb.bias ? jb.bias[c] : 0.f;
            float b1v = jb.bias ? jb.bias[c + 1] : 0.f;
            if (ra < n) {
                jb.C[(size_t)ra * FDIM + c]     = acc[s][0] + b0v;
                jb.C[(size_t)ra * FDIM + c + 1] = acc[s][1] + b1v;
            }
            if (rb < n) {
                jb.C[(size_t)rb * FDIM + c]     = acc[s][2] + b0v;
                jb.C[(size_t)rb * FDIM + c + 1] = acc[s][3] + b1v;
            }
        }
    }

    if (jb.al) {
        float pl0 = 0.f, pr0 = 0.f, pl1 = 0.f, pr1 = 0.f;
        #pragma unroll
        for (int s = 0; s < 5; s++) {
            int c = c0w + s * 8 + cq2;
            float w0 = s_al[c], w1 = s_al[c + 1];
            float v0 = s_ar[c], v1 = s_ar[c + 1];
            pl0 += acc[s][0] * w0 + acc[s][1] * w1;
            pr0 += acc[s][0] * v0 + acc[s][1] * v1;
            pl1 += acc[s][2] * w0 + acc[s][3] * w1;
            pr1 += acc[s][2] * v0 + acc[s][3] * v1;
        }
        #pragma unroll
        for (int o = 1; o <= 2; o <<= 1) {
            pl0 += __shfl_xor_sync(0xffffffffu, pl0, o);
            pr0 += __shfl_xor_sync(0xffffffffu, pr0, o);
            pl1 += __shfl_xor_sync(0xffffffffu, pl1, o);
            pr1 += __shfl_xor_sync(0xffffffffu, pr1, o);
        }
        if (kq == 0) {
            int ra = m0 + rl, rb = ra + 8;
            s_elr[wn][0][ra] = pl0; s_elr[wn][1][ra] = pr0;
            s_elr[wn][0][rb] = pl1; s_elr[wn][1][rb] = pr1;
        }
        __syncthreads();
        if (tid < 64) {
            int r = row0 + tid;
            if (r < n) {
                jb.el[r] = s_elr[0][0][tid] + s_elr[1][0][tid]
                         + s_elr[2][0][tid] + s_elr[3][0][tid];
                jb.er[r] = s_elr[0][1][tid] + s_elr[1][1][tid]
                         + s_elr[2][1][tid] + s_elr[3][1][tid];
            }
        }
    }
}

// ---------------- per-node kernels ----------------
__global__ void concat_kernel(const float* __restrict__ aft, const float* __restrict__ sta) {
    int idx = blockIdx.x * blockDim.x + threadIdx.x;
    if (idx >= NMAX * FDIM) return;
    int nd = idx / FDIM, f = idx % FDIM;
    float v = 0.0f;
    if (nd < N_NODES) v = (f < 144) ? aft[nd * 144 + f] : sta[nd * 16 + (f - 144)];
    g_X0[idx] = v;
}

// ---- batched fused edge-softmax + aggregation: one warp per node, blockIdx.y = job ----
__global__ void gather_batched(GatherBatch gbt) {
    const GatherJob jb = gbt.j[blockIdx.y];
    int gid = blockIdx.x * blockDim.x + threadIdx.x;
    int w = gid >> 5;
    int lane = threadIdx.x & 31;
    if (w >= jb.n) return;

    const int start = jb.off[w];
    const int end   = jb.off[w + 1];
    const float er_d = jb.er[w];
    const float* __restrict__ elp = jb.el;
    const int* __restrict__ ssrc = jb.ssrc;
    const float* __restrict__ Hp = jb.H;

    float mi = -INFINITY, si = 0.f;
    for (int j = start + lane; j < end; j += 32) {
        float z = elp[ssrc[j]] + er_d;
        z = (z > 0.f) ? z : 0.2f * z;
        if (z > mi) {
            si = si * expf(mi - z) + 1.0f;
            mi = z;
        } else {
            si += expf(z - mi);
        }
    }
    float mx = warp_max(mi);
    if (!isfinite(mx)) mx = 0.0f;
    float s = warp_sum(si * expf(mi - mx));
    const float inv = 1.0f / fmaxf(s, 1e-9f);

    float acc0 = 0.f, acc1 = 0.f, acc2 = 0.f, acc3 = 0.f, acc4 = 0.f;
    for (int g0 = start; g0 < end; g0 += 32) {
        int j = g0 + lane;
        int sN = 0; float wgt = 0.f;
        if (j < end) {
            sN = ssrc[j];
            float z = elp[sN] + er_d;
            z = (z > 0.f) ? z : 0.2f * z;
            wgt = expf(z - mx) * inv;
        }
        int cnt = min(32, end - g0);
        for (int k = 0; k < cnt; k++) {
            float wk = __shfl_sync(0xffffffffu, wgt, k);
            int   sk = __shfl_sync(0xffffffffu, sN,  k);
            const float* hp = Hp + (size_t)sk * FDIM;
            acc0 += wk * hp[lane];
            acc1 += wk * hp[lane + 32];
            acc2 += wk * hp[lane + 64];
            acc3 += wk * hp[lane + 96];
            acc4 += wk * hp[lane + 128];
        }
    }

    float* od = jb.dest + (size_t)w * FDIM;
    const float* b = jb.b;
    float v;
    v = acc0 + b[lane];       od[lane]       = (v > 0.f) ? v : 0.01f * v;
    v = acc1 + b[lane + 32];  od[lane + 32]  = (v > 0.f) ? v : 0.01f * v;
    v = acc2 + b[lane + 64];  od[lane + 64]  = (v > 0.f) ? v : 0.01f * v;
    v = acc3 + b[lane + 96];  od[lane + 96]  = (v > 0.f) ? v : 0.01f * v;
    v = acc4 + b[lane + 128]; od[lane + 128] = (v > 0.f) ? v : 0.01f * v;
}

// ---------------- precompute M1 = Wq @ Wk^T, v1 = Wk @ bq ----------------
__global__ void prep_m1_kernel(const float* __restrict__ Wq, const float* __restrict__ Wk,
                               const float* __restrict__ bq) {
    int idx = blockIdx.x * blockDim.x + threadIdx.x;
    if (idx < FDIM * FDIM) {
        int f = idx / FDIM, g = idx % FDIM;
        float s = 0.f;
        #pragma unroll 8
        for (int d = 0; d < DKDIM; d++) s += Wq[f * DKDIM + d] * Wk[g * DKDIM + d];
        g_M1[idx] = s;
    }
    if (idx < FDIM) {
        float s = 0.f;
        #pragma unroll 8
        for (int d = 0; d < DKDIM; d++) s += bq[d] * Wk[idx * DKDIM + d];
        g_v1[idx] = s;
    }
}

// ---------------- final attention merge + classifier + log_softmax ----------------
__global__ void attn_kernel(const float* __restrict__ Wl, const float* __restrict__ bl,
                            float* __restrict__ out) {
    int gid = blockIdx.x * blockDim.x + threadIdx.x;
    int w = gid >> 5;
    int lane = threadIdx.x & 31;
    if (w >= N_NODES) return;

    const float* ur = g_U + (size_t)w * FDIM;
    float u[5];
    #pragma unroll
    for (int t = 0; t < 5; t++) u[t] = ur[lane + 32 * t];

    const float* Ap[5] = { g_A1 + (size_t)w * FDIM, g_A2 + (size_t)w * FDIM,
                           g_A3 + (size_t)w * FDIM, g_A4 + (size_t)w * FDIM,
                           g_Ady + (size_t)w * FDIM };
    float a[5][5];
    #pragma unroll
    for (int j = 0; j < 5; j++)
        #pragma unroll
        for (int t = 0; t < 5; t++) a[j][t] = Ap[j][lane + 32 * t];

    float logit[5];
    #pragma unroll
    for (int j = 0; j < 5; j++) {
        float p = 0.f;
        #pragma unroll
        for (int t = 0; t < 5; t++) p += u[t] * a[j][t];
        logit[j] = warp_sum(p) * 0.125f;
    }

    float mx = logit[0];
    #pragma unroll
    for (int j = 1; j < 5; j++) mx = fmaxf(mx, logit[j]);
    float aw[5], asum = 0.f;
    #pragma unroll
    for (int j = 0; j < 5; j++) { aw[j] = expf(logit[j] - mx); asum += aw[j]; }
    float inv = 1.0f / asum;

    const float* xr = g_X0 + (size_t)w * FDIM;
    float y0 = 0.f, y1 = 0.f;
    #pragma unroll
    for (int t = 0; t < 5; t++) {
        int f = lane + 32 * t;
        float mf = 0.f;
        #pragma unroll
        for (int j = 0; j < 5; j++) mf += aw[j] * a[j][t];
        mf *= inv;
        float xv = xr[f];
        y0 += xv * Wl[2 * f]     + mf * Wl[2 * (160 + f)];
        y1 += xv * Wl[2 * f + 1] + mf * Wl[2 * (160 + f) + 1];
    }
    y0 = warp_sum(y0);
    y1 = warp_sum(y1);
    if (lane == 0) {
        y0 += bl[0]; y1 += bl[1];
        float m2 = fmaxf(y0, y1);
        float lz = m2 + logf(expf(y0 - m2) + expf(y1 - m2));
        out[2 * w]     = y0 - lz;
        out[2 * w + 1] = y1 - lz;
    }
}

// ---------------- host orchestration ----------------
static inline int cdiv(int a, int b) { return (a + b - 1) / b; }

extern "C" void kernel_launch(void* const* d_in, const int* in_sizes, int n_in,
                              void* d_out, int out_size) {
    bool sigOrder = (in_sizes[2] == 7 * FDIM * FDIM);
    int wbase = sigOrder ? 2 : 16;
    int ebase = sigOrder ? 12 : 2;

    const float* aft   = (const float*)d_in[0];
    const float* sta   = (const float*)d_in[1];
    const float* gat_W = (const float*)d_in[wbase + 0];
    const float* gat_al= (const float*)d_in[wbase + 1];
    const float* gat_ar= (const float*)d_in[wbase + 2];
    const float* gat_b = (const float*)d_in[wbase + 3];
    const float* Wq    = (const float*)d_in[wbase + 4];
    const float* bq    = (const float*)d_in[wbase + 5];
    const float* Wk    = (const float*)d_in[wbase + 6];
    const float* Wl    = (const float*)d_in[wbase + 8];
    const float* bl    = (const float*)d_in[wbase + 9];
    const int* e[14];
    for (int i = 0; i < 14; i++) e[i] = (const int*)d_in[ebase + i];

    void *pX0, *pHb, *pT3, *pT5, *pA1, *pA2, *pA3, *pA4, *pAdy, *pU, *pM1, *pV1,
         *pElB, *pErB, *pOff, *pSrc;
    cudaGetSymbolAddress(&pX0, g_X0);
    cudaGetSymbolAddress(&pHb, g_Hb);
    cudaGetSymbolAddress(&pT3, g_T3);
    cudaGetSymbolAddress(&pT5, g_T5);
    cudaGetSymbolAddress(&pA1, g_A1);
    cudaGetSymbolAddress(&pA2, g_A2);
    cudaGetSymbolAddress(&pA3, g_A3);
    cudaGetSymbolAddress(&pA4, g_A4);
    cudaGetSymbolAddress(&pAdy,g_Ady);
    cudaGetSymbolAddress(&pU,  g_U);
    cudaGetSymbolAddress(&pM1, g_M1);
    cudaGetSymbolAddress(&pV1, g_v1);
    cudaGetSymbolAddress(&pElB,g_elB);
    cudaGetSymbolAddress(&pErB,g_erB);
    cudaGetSymbolAddress(&pOff,g_offB);
    cudaGetSymbolAddress(&pSrc,g_ssrcB);

    float* X0  = (float*)pX0;
    float* T3  = (float*)pT3;
    float* T5  = (float*)pT5;
    float* A1  = (float*)pA1;
    float* A2  = (float*)pA2;
    float* A3  = (float*)pA3;
    float* A4  = (float*)pA4;
    float* Ady = (float*)pAdy;
    float* Ub  = (float*)pU;
    float* M1  = (float*)pM1;
    float* V1  = (float*)pV1;
    auto Hbuf = [&](int i) { return (float*)pHb + (size_t)i * NMAX * FDIM; };
    auto ElB  = [&](int i) { return (float*)pElB + (size_t)i * NMAX; };
    auto ErB  = [&](int i) { return (float*)pErB + (size_t)i * NMAX; };
    auto Off  = [&](int g) { return (int*)pOff + (size_t)g * OFFSTR; };
    auto Ssrc = [&](int g) { return (int*)pSrc + (size_t)g * NEDGE; };

    const int TPB = 256;
    const int GX = cdiv(NMAX, 64);
    const int GW = cdiv(NMAX * 32, TPB);

    EdgePtrs ep;
    for (int g = 0; g < NGRAPH; g++) { ep.src[g] = e[2 * g]; ep.dst[g] = e[2 * g + 1]; }

    int nL[7] = { N_NODES, N_NODES, N_NODES, N_NODES + 2, N_NODES + 2,
                  N_NODES + 20, N_NODES + 20 };

    batched_zero_kernel<<<cdiv(NGRAPH * NMAX / 4, TPB), TPB>>>();
    batched_hist_kernel<<<cdiv(NGRAPH * NEDGE, TPB), TPB>>>(ep);
    concat_kernel<<<cdiv(NMAX * FDIM, TPB), TPB>>>(aft, sta);

    // ---- launch 3 (ncu target): batched GEMM A — layers {0,1,2,3,5} from X0 ----
    GemmBatch ga;
    int laA[5] = { 0, 1, 2, 3, 5 };
    for (int k = 0; k < 5; k++) {
        int wi = laA[k];
        ga.j[k] = { X0, gat_W + (size_t)wi * FDIM * FDIM, nullptr,
                    gat_al + wi * FDIM, gat_ar + wi * FDIM,
                    Hbuf(k), ElB(k), ErB(k), nL[wi] };
    }
    gemm_tc_batched<<<dim3(GX, 5), 512>>>(ga);

    prep_m1_kernel<<<cdiv(FDIM * FDIM, TPB), TPB>>>(Wq, Wk, bq);
    batched_scan_kernel<<<NGRAPH, 1024>>>();
    batched_fill_kernel<<<cdiv(NGRAPH * NEDGE, TPB), TPB>>>(ep);

    GatherBatch gta;
    float* destA[5] = { Ady, A1, A2, T3, T5 };
    for (int k = 0; k < 5; k++) {
        int wi = laA[k];
        gta.j[k] = { gat_b + wi * FDIM, Hbuf(k), destA[k],
                     ElB(k), ErB(k), Off(wi), Ssrc(wi), nL[wi] };
    }
    gather_batched<<<dim3(GW, 5), TPB>>>(gta);

    GemmBatch gbB;
    gbB.j[0] = { T3, gat_W + (size_t)4 * FDIM * FDIM, nullptr,
                 gat_al + 4 * FDIM, gat_ar + 4 * FDIM,
                 Hbuf(0), ElB(0), ErB(0), nL[4] };
    gbB.j[1] = { T5, gat_W + (size_t)6 * FDIM * FDIM, nullptr,
                 gat_al + 6 * FDIM, gat_ar + 6 * FDIM,
                 Hbuf(1), ElB(1), ErB(1), nL[6] };
    gbB.j[2] = { X0, M1, V1, nullptr, nullptr, Ub, nullptr, nullptr, N_NODES };
    gbB.j[3] = gbB.j[2];
    gbB.j[4] = gbB.j[2];
    gemm_tc_batched<<<dim3(GX, 3), 512>>>(gbB);

    GatherBatch gtb;
    gtb.j[0] = { gat_b + 4 * FDIM, Hbuf(0), A3, ElB(0), ErB(0), Off(4), Ssrc(4), nL[4] };
    gtb.j[1] = { gat_b + 6 * FDIM, Hbuf(1), A4, ElB(1), ErB(1), Off(6), Ssrc(6), nL[6] };
    gtb.j[2] = gtb.j[0];
    gtb.j[3] = gtb.j[0];
    gtb.j[4] = gtb.j[0];
    gather_batched<<<dim3(GW, 2), TPB>>>(gtb);

    attn_kernel<<<cdiv(N_NODES * 32, TPB), TPB>>>(Wl, bl, (float*)d_out);
    (void)n_in; (void)out_size;
}

// round 16
// speedup vs baseline: 1.2283x; 1.2283x over previous
#include <cuda_runtime.h>
#include <cuda_bf16.h>
#include <math.h>
#include <stdint.h>

#define N_NODES 50000
#define FDIM    160
#define NMAX    50020   // N + S_EXTRA(20); divisible by 4
#define NEDGE   500000
#define DKDIM   64
#define NGRAPH  7
#define OFFSTR  (NMAX + 4)   // per-graph offset stride, 16B multiple

// ---------------- static device scratch (no runtime allocation) ----------------
__device__ float g_X0 [NMAX * FDIM];
__device__ float g_Hb [5][NMAX * FDIM];   // per-job GEMM outputs
__device__ float g_T3 [NMAX * FDIM];
__device__ float g_T5 [NMAX * FDIM];
__device__ float g_A1 [NMAX * FDIM];
__device__ float g_A2 [NMAX * FDIM];
__device__ float g_A3 [NMAX * FDIM];
__device__ float g_A4 [NMAX * FDIM];
__device__ float g_Ady[NMAX * FDIM];
__device__ float g_U  [NMAX * FDIM];
__device__ float g_M1 [FDIM * FDIM];
__device__ float g_v1 [FDIM];
__device__ float g_elB[5][NMAX];
__device__ float g_erB[5][NMAX];
__device__ __align__(16) int g_cntB [NGRAPH * NMAX];
__device__ __align__(16) int g_curB [NGRAPH * NMAX];
__device__ __align__(16) int g_offB [NGRAPH * OFFSTR];
__device__ int   g_ssrcB[NGRAPH * NEDGE];

struct EdgePtrs { const int* src[NGRAPH]; const int* dst[NGRAPH]; };

struct GemmJob {
    const float* A; const float* W; const float* bias;
    const float* al; const float* ar;
    float* C; float* el; float* er; int n;
};
struct GemmBatch { GemmJob j[5]; };

struct GatherJob {
    const float* b; const float* H; float* dest;
    const float* el; const float* er;
    const int* off; const int* ssrc; int n;
};
struct GatherBatch { GatherJob j[5]; };

// ---------------- helpers ----------------
__device__ __forceinline__ float warp_sum(float v) {
    #pragma unroll
    for (int o = 16; o > 0; o >>= 1) v += __shfl_xor_sync(0xffffffffu, v, o);
    return v;
}
__device__ __forceinline__ float warp_max(float v) {
    #pragma unroll
    for (int o = 16; o > 0; o >>= 1) v = fmaxf(v, __shfl_xor_sync(0xffffffffu, v, o));
    return v;
}

// bf16 split of a k-pair (x, y): hi = bf16(v), lo = bf16(v - float(hi)); packed bf16x2
__device__ __forceinline__ void bf16_split_pair(float x, float y,
                                                uint32_t& hiP, uint32_t& loP) {
    __nv_bfloat16 hx = __float2bfloat16(x);
    __nv_bfloat16 hy = __float2bfloat16(y);
    __nv_bfloat16 lx = __float2bfloat16(x - __bfloat162float(hx));
    __nv_bfloat16 ly = __float2bfloat16(y - __bfloat162float(hy));
    hiP = (uint32_t)__bfloat16_as_ushort(hx) | ((uint32_t)__bfloat16_as_ushort(hy) << 16);
    loP = (uint32_t)__bfloat16_as_ushort(lx) | ((uint32_t)__bfloat16_as_ushort(ly) << 16);
}

__device__ __forceinline__ void mma16(float acc[4], const uint32_t a[4],
                                      uint32_t b0, uint32_t b1) {
    asm volatile(
        "mma.sync.aligned.m16n8k16.row.col.f32.bf16.bf16.f32 "
        "{%0,%1,%2,%3}, {%4,%5,%6,%7}, {%8,%9}, {%0,%1,%2,%3};"
        : "+f"(acc[0]), "+f"(acc[1]), "+f"(acc[2]), "+f"(acc[3])
        : "r"(a[0]), "r"(a[1]), "r"(a[2]), "r"(a[3]), "r"(b0), "r"(b1));
}

// ---------------- batched CSR build ----------------
__global__ void batched_zero_kernel() {
    int i = blockIdx.x * blockDim.x + threadIdx.x;
    int n4 = NGRAPH * NMAX / 4;
    if (i < n4) {
        ((int4*)g_cntB)[i] = make_int4(0, 0, 0, 0);
        ((int4*)g_curB)[i] = make_int4(0, 0, 0, 0);
    }
}

__global__ void batched_hist_kernel(EdgePtrs ep) {
    int i = blockIdx.x * blockDim.x + threadIdx.x;
    if (i >= NGRAPH * NEDGE) return;
    int g = i / NEDGE, j = i - g * NEDGE;
    atomicAdd(&g_cntB[g * NMAX + ep.dst[g][j]], 1);
}

__global__ void batched_scan_kernel() {
    const int b = blockIdx.x;
    const int t = threadIdx.x;
    const int* cnt = g_cntB + b * NMAX;
    int* off = g_offB + b * OFFSTR;
    const int n4 = NMAX / 4;
    const int C4 = (n4 + 1023) / 1024;
    __shared__ int part[1024];

    int s = 0;
    for (int i = 0; i < C4; i++) {
        int idx = t * C4 + i;
        if (idx < n4) {
            int4 v = ((const int4*)cnt)[idx];
            s += v.x + v.y + v.z + v.w;
        }
    }
    part[t] = s;
    __syncthreads();
    for (int o = 1; o < 1024; o <<= 1) {
        int u = (t >= o) ? part[t - o] : 0;
        __syncthreads();
        part[t] += u;
        __syncthreads();
    }
    int run = part[t] - s;

    for (int i = 0; i < C4; i++) {
        int idx = t * C4 + i;
        if (idx < n4) {
            int4 v = ((const int4*)cnt)[idx];
            int4 o;
            o.x = run; run += v.x;
            o.y = run; run += v.y;
            o.z = run; run += v.z;
            o.w = run; run += v.w;
            ((int4*)off)[idx] = o;
        }
    }
    if (t == 1023) off[NMAX] = run;
}

__global__ void batched_fill_kernel(EdgePtrs ep) {
    int i = blockIdx.x * blockDim.x + threadIdx.x;
    if (i >= NGRAPH * NEDGE) return;
    int g = i / NEDGE, j = i - g * NEDGE;
    int d = ep.dst[g][j];
    int slot = g_offB[g * OFFSTR + d] + atomicAdd(&g_curB[g * NMAX + d], 1);
    g_ssrcB[g * NEDGE + slot] = ep.src[g][j];
}

// ---------------- batched bf16 tensor-core GEMM (3-term split, m16n8k16) ----------------
// 256 threads = 8 warps (4m x 2n); tile 64 x 160; K=16 per mma.
__global__ __launch_bounds__(256)
void gemm_tc_batched(GemmBatch gb) {
    const GemmJob jb = gb.j[blockIdx.y];
    const int n = jb.n;
    const int row0 = blockIdx.x * 64;
    if (row0 >= n) return;   // uniform per block

    __shared__ uint32_t AsHi[64][12];     // [row][k-pair], pad 12 -> conflict-free
    __shared__ uint32_t AsLo[64][12];
    __shared__ uint32_t BsHi[8][168];     // [k-pair][col], pad 168
    __shared__ uint32_t BsLo[8][168];
    __shared__ float    s_al[FDIM], s_ar[FDIM];
    __shared__ float    s_elr[2][2][64];

    const float* __restrict__ A = jb.A;
    const float* __restrict__ B = jb.W;

    const int tid  = threadIdx.x;
    const int wid  = tid >> 5;
    const int lane = tid & 31;
    const int wm   = wid & 3;
    const int wn   = wid >> 2;
    const int m0   = wm * 16;
    const int c0w  = wn * 80;
    const int rl   = lane >> 2;
    const int kq   = lane & 3;

    if (jb.al) {
        for (int i = tid; i < FDIM; i += 256) { s_al[i] = jb.al[i]; s_ar[i] = jb.ar[i]; }
    }

    float acc[10][4];
    #pragma unroll
    for (int s = 0; s < 10; s++)
        #pragma unroll
        for (int q = 0; q < 4; q++) acc[s][q] = 0.0f;

    for (int k0 = 0; k0 < FDIM; k0 += 16) {
        // stage A 64x16 -> packed bf16x2 hi/lo (k-pairs)
        {
            int m = tid >> 2, kc = (tid & 3) * 4;   // k offsets kc..kc+3 -> pairs kc/2, kc/2+1
            int r = row0 + m;
            float4 v = (r < n) ? *(const float4*)(A + (size_t)r * FDIM + k0 + kc)
                               : make_float4(0.f, 0.f, 0.f, 0.f);
            uint32_t h01, l01, h23, l23;
            bf16_split_pair(v.x, v.y, h01, l01);
            bf16_split_pair(v.z, v.w, h23, l23);
            int p = kc >> 1;
            *(uint2*)&AsHi[m][p] = make_uint2(h01, h23);
            *(uint2*)&AsLo[m][p] = make_uint2(l01, l23);
        }
        // stage B 16x160 -> packed bf16x2 hi/lo: Bs[p][c] = pack(B[2p][c], B[2p+1][c])
        for (int i = tid; i < 8 * 40; i += 256) {
            int p = i / 40, c4 = i - p * 40;
            const float* rowA = B + (size_t)(k0 + 2 * p) * FDIM + c4 * 4;
            const float* rowB = rowA + FDIM;
            float4 va = *(const float4*)rowA;
            float4 vb = *(const float4*)rowB;
            uint32_t h0, l0, h1, l1, h2, l2, h3, l3;
            bf16_split_pair(va.x, vb.x, h0, l0);
            bf16_split_pair(va.y, vb.y, h1, l1);
            bf16_split_pair(va.z, vb.z, h2, l2);
            bf16_split_pair(va.w, vb.w, h3, l3);
            *(uint4*)&BsHi[p][c4 * 4] = make_uint4(h0, h1, h2, h3);
            *(uint4*)&BsLo[p][c4 * 4] = make_uint4(l0, l1, l2, l3);
        }
        __syncthreads();

        // one K=16 mma step per k0 chunk
        uint32_t ah[4], alo[4];
        ah[0]  = AsHi[m0 + rl][kq];
        ah[1]  = AsHi[m0 + rl + 8][kq];
        ah[2]  = AsHi[m0 + rl][kq + 4];
        ah[3]  = AsHi[m0 + rl + 8][kq + 4];
        alo[0] = AsLo[m0 + rl][kq];
        alo[1] = AsLo[m0 + rl + 8][kq];
        alo[2] = AsLo[m0 + rl][kq + 4];
        alo[3] = AsLo[m0 + rl + 8][kq + 4];
        #pragma unroll
        for (int s = 0; s < 10; s++) {
            const int cc = c0w + s * 8 + rl;
            uint32_t bh0 = BsHi[kq][cc];
            uint32_t bh1 = BsHi[kq + 4][cc];
            uint32_t bl0 = BsLo[kq][cc];
            uint32_t bl1 = BsLo[kq + 4][cc];
            mma16(acc[s], ah,  bh0, bh1);   // hi*hi
            mma16(acc[s], alo, bh0, bh1);   // lo*hi
            mma16(acc[s], ah,  bl0, bl1);   // hi*lo
        }
        __syncthreads();
    }

    const int cq2 = kq * 2;
    {
        int ra = row0 + m0 + rl;
        int rb = ra + 8;
        #pragma unroll
        for (int s = 0; s < 10; s++) {
            int c = c0w + s * 8 + cq2;
            float b0v = jb.bias ? jb.bias[c] : 0.f;
            float b1v = jb.bias ? jb.bias[c + 1] : 0.f;
            if (ra < n) {
                jb.C[(size_t)ra * FDIM + c]     = acc[s][0] + b0v;
                jb.C[(size_t)ra * FDIM + c + 1] = acc[s][1] + b1v;
            }
            if (rb < n) {
                jb.C[(size_t)rb * FDIM + c]     = acc[s][2] + b0v;
                jb.C[(size_t)rb * FDIM + c + 1] = acc[s][3] + b1v;
            }
        }
    }

    if (jb.al) {
        float pl0 = 0.f, pr0 = 0.f, pl1 = 0.f, pr1 = 0.f;
        #pragma unroll
        for (int s = 0; s < 10; s++) {
            int c = c0w + s * 8 + cq2;
            float w0 = s_al[c], w1 = s_al[c + 1];
            float v0 = s_ar[c], v1 = s_ar[c + 1];
            pl0 += acc[s][0] * w0 + acc[s][1] * w1;
            pr0 += acc[s][0] * v0 + acc[s][1] * v1;
            pl1 += acc[s][2] * w0 + acc[s][3] * w1;
            pr1 += acc[s][2] * v0 + acc[s][3] * v1;
        }
        #pragma unroll
        for (int o = 1; o <= 2; o <<= 1) {
            pl0 += __shfl_xor_sync(0xffffffffu, pl0, o);
            pr0 += __shfl_xor_sync(0xffffffffu, pr0, o);
            pl1 += __shfl_xor_sync(0xffffffffu, pl1, o);
            pr1 += __shfl_xor_sync(0xffffffffu, pr1, o);
        }
        if (kq == 0) {
            int ra = m0 + rl, rb = ra + 8;
            s_elr[wn][0][ra] = pl0; s_elr[wn][1][ra] = pr0;
            s_elr[wn][0][rb] = pl1; s_elr[wn][1][rb] = pr1;
        }
        __syncthreads();
        if (tid < 64) {
            int r = row0 + tid;
            if (r < n) {
                jb.el[r] = s_elr[0][0][tid] + s_elr[1][0][tid];
                jb.er[r] = s_elr[0][1][tid] + s_elr[1][1][tid];
            }
        }
    }
}

// ---------------- per-node kernels ----------------
__global__ void concat_kernel(const float* __restrict__ aft, const float* __restrict__ sta) {
    int idx = blockIdx.x * blockDim.x + threadIdx.x;
    if (idx >= NMAX * FDIM) return;
    int nd = idx / FDIM, f = idx % FDIM;
    float v = 0.0f;
    if (nd < N_NODES) v = (f < 144) ? aft[nd * 144 + f] : sta[nd * 16 + (f - 144)];
    g_X0[idx] = v;
}

// ---- batched fused edge-softmax + aggregation: one warp per node, blockIdx.y = job ----
__global__ void gather_batched(GatherBatch gbt) {
    const GatherJob jb = gbt.j[blockIdx.y];
    int gid = blockIdx.x * blockDim.x + threadIdx.x;
    int w = gid >> 5;
    int lane = threadIdx.x & 31;
    if (w >= jb.n) return;

    const int start = jb.off[w];
    const int end   = jb.off[w + 1];
    const float er_d = jb.er[w];
    const float* __restrict__ elp = jb.el;
    const int* __restrict__ ssrc = jb.ssrc;
    const float* __restrict__ Hp = jb.H;

    float mi = -INFINITY, si = 0.f;
    for (int j = start + lane; j < end; j += 32) {
        float z = elp[ssrc[j]] + er_d;
        z = (z > 0.f) ? z : 0.2f * z;
        if (z > mi) {
            si = si * expf(mi - z) + 1.0f;
            mi = z;
        } else {
            si += expf(z - mi);
        }
    }
    float mx = warp_max(mi);
    if (!isfinite(mx)) mx = 0.0f;
    float s = warp_sum(si * expf(mi - mx));
    const float inv = 1.0f / fmaxf(s, 1e-9f);

    float acc0 = 0.f, acc1 = 0.f, acc2 = 0.f, acc3 = 0.f, acc4 = 0.f;
    for (int g0 = start; g0 < end; g0 += 32) {
        int j = g0 + lane;
        int sN = 0; float wgt = 0.f;
        if (j < end) {
            sN = ssrc[j];
            float z = elp[sN] + er_d;
            z = (z > 0.f) ? z : 0.2f * z;
            wgt = expf(z - mx) * inv;
        }
        int cnt = min(32, end - g0);
        for (int k = 0; k < cnt; k++) {
            float wk = __shfl_sync(0xffffffffu, wgt, k);
            int   sk = __shfl_sync(0xffffffffu, sN,  k);
            const float* hp = Hp + (size_t)sk * FDIM;
            acc0 += wk * hp[lane];
            acc1 += wk * hp[lane + 32];
            acc2 += wk * hp[lane + 64];
            acc3 += wk * hp[lane + 96];
            acc4 += wk * hp[lane + 128];
        }
    }

    float* od = jb.dest + (size_t)w * FDIM;
    const float* b = jb.b;
    float v;
    v = acc0 + b[lane];       od[lane]       = (v > 0.f) ? v : 0.01f * v;
    v = acc1 + b[lane + 32];  od[lane + 32]  = (v > 0.f) ? v : 0.01f * v;
    v = acc2 + b[lane + 64];  od[lane + 64]  = (v > 0.f) ? v : 0.01f * v;
    v = acc3 + b[lane + 96];  od[lane + 96]  = (v > 0.f) ? v : 0.01f * v;
    v = acc4 + b[lane + 128]; od[lane + 128] = (v > 0.f) ? v : 0.01f * v;
}

// ---------------- precompute M1 = Wq @ Wk^T, v1 = Wk @ bq ----------------
__global__ void prep_m1_kernel(const float* __restrict__ Wq, const float* __restrict__ Wk,
                               const float* __restrict__ bq) {
    int idx = blockIdx.x * blockDim.x + threadIdx.x;
    if (idx < FDIM * FDIM) {
        int f = idx / FDIM, g = idx % FDIM;
        float s = 0.f;
        #pragma unroll 8
        for (int d = 0; d < DKDIM; d++) s += Wq[f * DKDIM + d] * Wk[g * DKDIM + d];
        g_M1[idx] = s;
    }
    if (idx < FDIM) {
        float s = 0.f;
        #pragma unroll 8
        for (int d = 0; d < DKDIM; d++) s += bq[d] * Wk[idx * DKDIM + d];
        g_v1[idx] = s;
    }
}

// ---------------- final attention merge + classifier + log_softmax ----------------
__global__ void attn_kernel(const float* __restrict__ Wl, const float* __restrict__ bl,
                            float* __restrict__ out) {
    int gid = blockIdx.x * blockDim.x + threadIdx.x;
    int w = gid >> 5;
    int lane = threadIdx.x & 31;
    if (w >= N_NODES) return;

    const float* ur = g_U + (size_t)w * FDIM;
    float u[5];
    #pragma unroll
    for (int t = 0; t < 5; t++) u[t] = ur[lane + 32 * t];

    const float* Ap[5] = { g_A1 + (size_t)w * FDIM, g_A2 + (size_t)w * FDIM,
                           g_A3 + (size_t)w * FDIM, g_A4 + (size_t)w * FDIM,
                           g_Ady + (size_t)w * FDIM };
    float a[5][5];
    #pragma unroll
    for (int j = 0; j < 5; j++)
        #pragma unroll
        for (int t = 0; t < 5; t++) a[j][t] = Ap[j][lane + 32 * t];

    float logit[5];
    #pragma unroll
    for (int j = 0; j < 5; j++) {
        float p = 0.f;
        #pragma unroll
        for (int t = 0; t < 5; t++) p += u[t] * a[j][t];
        logit[j] = warp_sum(p) * 0.125f;
    }

    float mx = logit[0];
    #pragma unroll
    for (int j = 1; j < 5; j++) mx = fmaxf(mx, logit[j]);
    float aw[5], asum = 0.f;
    #pragma unroll
    for (int j = 0; j < 5; j++) { aw[j] = expf(logit[j] - mx); asum += aw[j]; }
    float inv = 1.0f / asum;

    const float* xr = g_X0 + (size_t)w * FDIM;
    float y0 = 0.f, y1 = 0.f;
    #pragma unroll
    for (int t = 0; t < 5; t++) {
        int f = lane + 32 * t;
        float mf = 0.f;
        #pragma unroll
        for (int j = 0; j < 5; j++) mf += aw[j] * a[j][t];
        mf *= inv;
        float xv = xr[f];
        y0 += xv * Wl[2 * f]     + mf * Wl[2 * (160 + f)];
        y1 += xv * Wl[2 * f + 1] + mf * Wl[2 * (160 + f) + 1];
    }
    y0 = warp_sum(y0);
    y1 = warp_sum(y1);
    if (lane == 0) {
        y0 += bl[0]; y1 += bl[1];
        float m2 = fmaxf(y0, y1);
        float lz = m2 + logf(expf(y0 - m2) + expf(y1 - m2));
        out[2 * w]     = y0 - lz;
        out[2 * w + 1] = y1 - lz;
    }
}

// ---------------- host orchestration ----------------
static inline int cdiv(int a, int b) { return (a + b - 1) / b; }

extern "C" void kernel_launch(void* const* d_in, const int* in_sizes, int n_in,
                              void* d_out, int out_size) {
    bool sigOrder = (in_sizes[2] == 7 * FDIM * FDIM);
    int wbase = sigOrder ? 2 : 16;
    int ebase = sigOrder ? 12 : 2;

    const float* aft   = (const float*)d_in[0];
    const float* sta   = (const float*)d_in[1];
    const float* gat_W = (const float*)d_in[wbase + 0];
    const float* gat_al= (const float*)d_in[wbase + 1];
    const float* gat_ar= (const float*)d_in[wbase + 2];
    const float* gat_b = (const float*)d_in[wbase + 3];
    const float* Wq    = (const float*)d_in[wbase + 4];
    const float* bq    = (const float*)d_in[wbase + 5];
    const float* Wk    = (const float*)d_in[wbase + 6];
    const float* Wl    = (const float*)d_in[wbase + 8];
    const float* bl    = (const float*)d_in[wbase + 9];
    const int* e[14];
    for (int i = 0; i < 14; i++) e[i] = (const int*)d_in[ebase + i];

    void *pX0, *pHb, *pT3, *pT5, *pA1, *pA2, *pA3, *pA4, *pAdy, *pU, *pM1, *pV1,
         *pElB, *pErB, *pOff, *pSrc;
    cudaGetSymbolAddress(&pX0, g_X0);
    cudaGetSymbolAddress(&pHb, g_Hb);
    cudaGetSymbolAddress(&pT3, g_T3);
    cudaGetSymbolAddress(&pT5, g_T5);
    cudaGetSymbolAddress(&pA1, g_A1);
    cudaGetSymbolAddress(&pA2, g_A2);
    cudaGetSymbolAddress(&pA3, g_A3);
    cudaGetSymbolAddress(&pA4, g_A4);
    cudaGetSymbolAddress(&pAdy,g_Ady);
    cudaGetSymbolAddress(&pU,  g_U);
    cudaGetSymbolAddress(&pM1, g_M1);
    cudaGetSymbolAddress(&pV1, g_v1);
    cudaGetSymbolAddress(&pElB,g_elB);
    cudaGetSymbolAddress(&pErB,g_erB);
    cudaGetSymbolAddress(&pOff,g_offB);
    cudaGetSymbolAddress(&pSrc,g_ssrcB);

    float* X0  = (float*)pX0;
    float* T3  = (float*)pT3;
    float* T5  = (float*)pT5;
    float* A1  = (float*)pA1;
    float* A2  = (float*)pA2;
    float* A3  = (float*)pA3;
    float* A4  = (float*)pA4;
    float* Ady = (float*)pAdy;
    float* Ub  = (float*)pU;
    float* M1  = (float*)pM1;
    float* V1  = (float*)pV1;
    auto Hbuf = [&](int i) { return (float*)pHb + (size_t)i * NMAX * FDIM; };
    auto ElB  = [&](int i) { return (float*)pElB + (size_t)i * NMAX; };
    auto ErB  = [&](int i) { return (float*)pErB + (size_t)i * NMAX; };
    auto Off  = [&](int g) { return (int*)pOff + (size_t)g * OFFSTR; };
    auto Ssrc = [&](int g) { return (int*)pSrc + (size_t)g * NEDGE; };

    const int TPB = 256;
    const int GX = cdiv(NMAX, 64);
    const int GW = cdiv(NMAX * 32, TPB);

    EdgePtrs ep;
    for (int g = 0; g < NGRAPH; g++) { ep.src[g] = e[2 * g]; ep.dst[g] = e[2 * g + 1]; }

    int nL[7] = { N_NODES, N_NODES, N_NODES, N_NODES + 2, N_NODES + 2,
                  N_NODES + 20, N_NODES + 20 };

    batched_zero_kernel<<<cdiv(NGRAPH * NMAX / 4, TPB), TPB>>>();
    batched_hist_kernel<<<cdiv(NGRAPH * NEDGE, TPB), TPB>>>(ep);
    concat_kernel<<<cdiv(NMAX * FDIM, TPB), TPB>>>(aft, sta);

    // ---- launch 3 (ncu target): batched GEMM A — layers {0,1,2,3,5} from X0 ----
    GemmBatch ga;
    int laA[5] = { 0, 1, 2, 3, 5 };
    for (int k = 0; k < 5; k++) {
        int wi = laA[k];
        ga.j[k] = { X0, gat_W + (size_t)wi * FDIM * FDIM, nullptr,
                    gat_al + wi * FDIM, gat_ar + wi * FDIM,
                    Hbuf(k), ElB(k), ErB(k), nL[wi] };
    }
    gemm_tc_batched<<<dim3(GX, 5), TPB>>>(ga);

    prep_m1_kernel<<<cdiv(FDIM * FDIM, TPB), TPB>>>(Wq, Wk, bq);
    batched_scan_kernel<<<NGRAPH, 1024>>>();
    batched_fill_kernel<<<cdiv(NGRAPH * NEDGE, TPB), TPB>>>(ep);

    GatherBatch gta;
    float* destA[5] = { Ady, A1, A2, T3, T5 };
    for (int k = 0; k < 5; k++) {
        int wi = laA[k];
        gta.j[k] = { gat_b + wi * FDIM, Hbuf(k), destA[k],
                     ElB(k), ErB(k), Off(wi), Ssrc(wi), nL[wi] };
    }
    gather_batched<<<dim3(GW, 5), TPB>>>(gta);

    GemmBatch gbB;
    gbB.j[0] = { T3, gat_W + (size_t)4 * FDIM * FDIM, nullptr,
                 gat_al + 4 * FDIM, gat_ar + 4 * FDIM,
                 Hbuf(0), ElB(0), ErB(0), nL[4] };
    gbB.j[1] = { T5, gat_W + (size_t)6 * FDIM * FDIM, nullptr,
                 gat_al + 6 * FDIM, gat_ar + 6 * FDIM,
                 Hbuf(1), ElB(1), ErB(1), nL[6] };
    gbB.j[2] = { X0, M1, V1, nullptr, nullptr, Ub, nullptr, nullptr, N_NODES };
    gbB.j[3] = gbB.j[2];
    gbB.j[4] = gbB.j[2];
    gemm_tc_batched<<<dim3(GX, 3), TPB>>>(gbB);

    GatherBatch gtb;
    gtb.j[0] = { gat_b + 4 * FDIM, Hbuf(0), A3, ElB(0), ErB(0), Off(4), Ssrc(4), nL[4] };
    gtb.j[1] = { gat_b + 6 * FDIM, Hbuf(1), A4, ElB(1), ErB(1), Off(6), Ssrc(6), nL[6] };
    gtb.j[2] = gtb.j[0];
    gtb.j[3] = gtb.j[0];
    gtb.j[4] = gtb.j[0];
    gather_batched<<<dim3(GW, 2), TPB>>>(gtb);

    attn_kernel<<<cdiv(N_NODES * 32, TPB), TPB>>>(Wl, bl, (float*)d_out);
    (void)n_in; (void)out_size;
}

// round 17
// speedup vs baseline: 1.2521x; 1.0194x over previous
#include <cuda_runtime.h>
#include <cuda_bf16.h>
#include <math.h>
#include <stdint.h>

#define N_NODES 50000
#define FDIM    160
#define NMAX    50020   // N + S_EXTRA(20); divisible by 4
#define NEDGE   500000
#define DKDIM   64
#define NGRAPH  7
#define OFFSTR  (NMAX + 4)   // per-graph offset stride, 16B multiple

// ---------------- static device scratch (no runtime allocation) ----------------
__device__ float g_X0 [NMAX * FDIM];
__device__ float g_Hb [5][NMAX * FDIM];   // per-job GEMM outputs
__device__ float g_T3 [NMAX * FDIM];
__device__ float g_T5 [NMAX * FDIM];
__device__ float g_A1 [NMAX * FDIM];
__device__ float g_A2 [NMAX * FDIM];
__device__ float g_A3 [NMAX * FDIM];
__device__ float g_A4 [NMAX * FDIM];
__device__ float g_Ady[NMAX * FDIM];
__device__ float g_U  [NMAX * FDIM];
__device__ float g_M1 [FDIM * FDIM];
__device__ float g_v1 [FDIM];
__device__ float g_elB[5][NMAX];
__device__ float g_erB[5][NMAX];
__device__ __align__(16) int g_cntB [NGRAPH * NMAX];
__device__ __align__(16) int g_curB [NGRAPH * NMAX];
__device__ __align__(16) int g_offB [NGRAPH * OFFSTR];
__device__ int   g_ssrcB[NGRAPH * NEDGE];

struct EdgePtrs { const int* src[NGRAPH]; const int* dst[NGRAPH]; };

struct GemmJob {
    const float* A; const float* W; const float* bias;
    const float* al; const float* ar;
    float* C; float* el; float* er; int n;
};
struct GemmBatch { GemmJob j[5]; };

struct GatherJob {
    const float* b; const float* H; float* dest;
    const float* el; const float* er;
    const int* off; const int* ssrc; int n;
};
struct GatherBatch { GatherJob j[5]; };

// ---------------- helpers ----------------
__device__ __forceinline__ float warp_sum(float v) {
    #pragma unroll
    for (int o = 16; o > 0; o >>= 1) v += __shfl_xor_sync(0xffffffffu, v, o);
    return v;
}
__device__ __forceinline__ float warp_max(float v) {
    #pragma unroll
    for (int o = 16; o > 0; o >>= 1) v = fmaxf(v, __shfl_xor_sync(0xffffffffu, v, o));
    return v;
}

// bf16 split of a pair (x, y): hi = bf16(v), lo = bf16(v - float(hi)); packed bf16x2
__device__ __forceinline__ void bf16_split_pair(float x, float y,
                                                uint32_t& hiP, uint32_t& loP) {
    __nv_bfloat16 hx = __float2bfloat16(x);
    __nv_bfloat16 hy = __float2bfloat16(y);
    __nv_bfloat16 lx = __float2bfloat16(x - __bfloat162float(hx));
    __nv_bfloat16 ly = __float2bfloat16(y - __bfloat162float(hy));
    hiP = (uint32_t)__bfloat16_as_ushort(hx) | ((uint32_t)__bfloat16_as_ushort(hy) << 16);
    loP = (uint32_t)__bfloat16_as_ushort(lx) | ((uint32_t)__bfloat16_as_ushort(ly) << 16);
}

__device__ __forceinline__ void mma16(float acc[4], const uint32_t a[4],
                                      uint32_t b0, uint32_t b1) {
    asm volatile(
        "mma.sync.aligned.m16n8k16.row.col.f32.bf16.bf16.f32 "
        "{%0,%1,%2,%3}, {%4,%5,%6,%7}, {%8,%9}, {%0,%1,%2,%3};"
        : "+f"(acc[0]), "+f"(acc[1]), "+f"(acc[2]), "+f"(acc[3])
        : "r"(a[0]), "r"(a[1]), "r"(a[2]), "r"(a[3]), "r"(b0), "r"(b1));
}

// ---------------- batched CSR build ----------------
__global__ void batched_zero_kernel() {
    int i = blockIdx.x * blockDim.x + threadIdx.x;
    int n4 = NGRAPH * NMAX / 4;
    if (i < n4) {
        ((int4*)g_cntB)[i] = make_int4(0, 0, 0, 0);
        ((int4*)g_curB)[i] = make_int4(0, 0, 0, 0);
    }
}

__global__ void batched_hist_kernel(EdgePtrs ep) {
    int i = blockIdx.x * blockDim.x + threadIdx.x;
    if (i >= NGRAPH * NEDGE) return;
    int g = i / NEDGE, j = i - g * NEDGE;
    atomicAdd(&g_cntB[g * NMAX + ep.dst[g][j]], 1);
}

__global__ void batched_scan_kernel() {
    const int b = blockIdx.x;
    const int t = threadIdx.x;
    const int* cnt = g_cntB + b * NMAX;
    int* off = g_offB + b * OFFSTR;
    const int n4 = NMAX / 4;
    const int C4 = (n4 + 1023) / 1024;
    __shared__ int part[1024];

    int s = 0;
    for (int i = 0; i < C4; i++) {
        int idx = t * C4 + i;
        if (idx < n4) {
            int4 v = ((const int4*)cnt)[idx];
            s += v.x + v.y + v.z + v.w;
        }
    }
    part[t] = s;
    __syncthreads();
    for (int o = 1; o < 1024; o <<= 1) {
        int u = (t >= o) ? part[t - o] : 0;
        __syncthreads();
        part[t] += u;
        __syncthreads();
    }
    int run = part[t] - s;

    for (int i = 0; i < C4; i++) {
        int idx = t * C4 + i;
        if (idx < n4) {
            int4 v = ((const int4*)cnt)[idx];
            int4 o;
            o.x = run; run += v.x;
            o.y = run; run += v.y;
            o.z = run; run += v.z;
            o.w = run; run += v.w;
            ((int4*)off)[idx] = o;
        }
    }
    if (t == 1023) off[NMAX] = run;
}

__global__ void batched_fill_kernel(EdgePtrs ep) {
    int i = blockIdx.x * blockDim.x + threadIdx.x;
    if (i >= NGRAPH * NEDGE) return;
    int g = i / NEDGE, j = i - g * NEDGE;
    int d = ep.dst[g][j];
    int slot = g_offB[g * OFFSTR + d] + atomicAdd(&g_curB[g * NMAX + d], 1);
    g_ssrcB[g * NEDGE + slot] = ep.src[g][j];
}

// ---------------- batched bf16 tensor-core GEMM (3-term split, double-buffered) ----------------
// 256 threads = 8 warps (4m x 2n); tile 64 x 160; K=16 per mma; 2-stage smem pipeline.
__global__ __launch_bounds__(256)
void gemm_tc_batched(GemmBatch gb) {
    const GemmJob jb = gb.j[blockIdx.y];
    const int n = jb.n;
    const int row0 = blockIdx.x * 64;
    if (row0 >= n) return;   // uniform per block

    __shared__ uint32_t AsHi[2][64][12];
    __shared__ uint32_t AsLo[2][64][12];
    __shared__ uint32_t BsHi[2][8][168];
    __shared__ uint32_t BsLo[2][8][168];
    __shared__ float    s_al[FDIM], s_ar[FDIM];
    __shared__ float    s_elr[2][2][64];

    const float* __restrict__ A = jb.A;
    const float* __restrict__ B = jb.W;

    const int tid  = threadIdx.x;
    const int wid  = tid >> 5;
    const int lane = tid & 31;
    const int wm   = wid & 3;
    const int wn   = wid >> 2;
    const int m0   = wm * 16;
    const int c0w  = wn * 80;
    const int rl   = lane >> 2;
    const int kq   = lane & 3;

    // staging coordinates (fixed per thread)
    const int sam = tid >> 2;                 // A: row within tile
    const int sak = (tid & 3) * 4;            // A: k offset (4 wide)
    const int sb0 = tid;                      // B: job indices tid, tid+256 (<320)
    const int sb1 = tid + 256;
    const int sb0p = sb0 / 40, sb0c = sb0 - sb0p * 40;
    const int sb1p = sb1 / 40, sb1c = sb1 - sb1p * 40;
    const bool hasB1 = (sb1 < 320);

    if (jb.al) {
        for (int i = tid; i < FDIM; i += 256) { s_al[i] = jb.al[i]; s_ar[i] = jb.ar[i]; }
    }

    float acc[10][4];
    #pragma unroll
    for (int s = 0; s < 10; s++)
        #pragma unroll
        for (int q = 0; q < 4; q++) acc[s][q] = 0.0f;

    // ---- helpers as lambdas over fixed coords ----
    auto loadA = [&](int k0, float4& pa) {
        int r = row0 + sam;
        pa = (r < n) ? *(const float4*)(A + (size_t)r * FDIM + k0 + sak)
                     : make_float4(0.f, 0.f, 0.f, 0.f);
    };
    auto loadB = [&](int k0, float4& b0a, float4& b0b, float4& b1a, float4& b1b) {
        {
            const float* rA = B + (size_t)(k0 + 2 * sb0p) * FDIM + sb0c * 4;
            b0a = *(const float4*)rA;
            b0b = *(const float4*)(rA + FDIM);
        }
        if (hasB1) {
            const float* rA = B + (size_t)(k0 + 2 * sb1p) * FDIM + sb1c * 4;
            b1a = *(const float4*)rA;
            b1b = *(const float4*)(rA + FDIM);
        }
    };
    auto storeA = [&](int buf, const float4& pa) {
        uint32_t h01, l01, h23, l23;
        bf16_split_pair(pa.x, pa.y, h01, l01);
        bf16_split_pair(pa.z, pa.w, h23, l23);
        int p = sak >> 1;
        *(uint2*)&AsHi[buf][sam][p] = make_uint2(h01, h23);
        *(uint2*)&AsLo[buf][sam][p] = make_uint2(l01, l23);
    };
    auto storeB = [&](int buf, const float4& b0a, const float4& b0b,
                      const float4& b1a, const float4& b1b) {
        {
            uint32_t h0, l0, h1, l1, h2, l2, h3, l3;
            bf16_split_pair(b0a.x, b0b.x, h0, l0);
            bf16_split_pair(b0a.y, b0b.y, h1, l1);
            bf16_split_pair(b0a.z, b0b.z, h2, l2);
            bf16_split_pair(b0a.w, b0b.w, h3, l3);
            *(uint4*)&BsHi[buf][sb0p][sb0c * 4] = make_uint4(h0, h1, h2, h3);
            *(uint4*)&BsLo[buf][sb0p][sb0c * 4] = make_uint4(l0, l1, l2, l3);
        }
        if (hasB1) {
            uint32_t h0, l0, h1, l1, h2, l2, h3, l3;
            bf16_split_pair(b1a.x, b1b.x, h0, l0);
            bf16_split_pair(b1a.y, b1b.y, h1, l1);
            bf16_split_pair(b1a.z, b1b.z, h2, l2);
            bf16_split_pair(b1a.w, b1b.w, h3, l3);
            *(uint4*)&BsHi[buf][sb1p][sb1c * 4] = make_uint4(h0, h1, h2, h3);
            *(uint4*)&BsLo[buf][sb1p][sb1c * 4] = make_uint4(l0, l1, l2, l3);
        }
    };

    // prologue: stage chunk 0 into buf 0
    {
        float4 pa, b0a, b0b, b1a, b1b;
        loadA(0, pa);
        loadB(0, b0a, b0b, b1a, b1b);
        storeA(0, pa);
        storeB(0, b0a, b0b, b1a, b1b);
    }
    __syncthreads();

    for (int c = 0; c < 10; c++) {
        const int cur = c & 1;
        const int nxt = cur ^ 1;
        const bool hasNext = (c + 1 < 10);
        const int k0n = (c + 1) * 16;

        // issue prefetch LDGs for next chunk (latency overlaps mma below)
        float4 pa, b0a, b0b, b1a, b1b;
        if (hasNext) {
            loadA(k0n, pa);
            loadB(k0n, b0a, b0b, b1a, b1b);
        }

        // compute on cur buffer
        uint32_t ah[4], alo[4];
        ah[0]  = AsHi[cur][m0 + rl][kq];
        ah[1]  = AsHi[cur][m0 + rl + 8][kq];
        ah[2]  = AsHi[cur][m0 + rl][kq + 4];
        ah[3]  = AsHi[cur][m0 + rl + 8][kq + 4];
        alo[0] = AsLo[cur][m0 + rl][kq];
        alo[1] = AsLo[cur][m0 + rl + 8][kq];
        alo[2] = AsLo[cur][m0 + rl][kq + 4];
        alo[3] = AsLo[cur][m0 + rl + 8][kq + 4];
        #pragma unroll
        for (int s = 0; s < 10; s++) {
            const int cc = c0w + s * 8 + rl;
            uint32_t bh0 = BsHi[cur][kq][cc];
            uint32_t bh1 = BsHi[cur][kq + 4][cc];
            uint32_t bl0 = BsLo[cur][kq][cc];
            uint32_t bl1 = BsLo[cur][kq + 4][cc];
            mma16(acc[s], ah,  bh0, bh1);
            mma16(acc[s], alo, bh0, bh1);
            mma16(acc[s], ah,  bl0, bl1);
        }

        // split + store prefetched data into nxt buffer
        if (hasNext) {
            storeA(nxt, pa);
            storeB(nxt, b0a, b0b, b1a, b1b);
        }
        __syncthreads();
    }

    const int cq2 = kq * 2;
    {
        int ra = row0 + m0 + rl;
        int rb = ra + 8;
        #pragma unroll
        for (int s = 0; s < 10; s++) {
            int c = c0w + s * 8 + cq2;
            float b0v = jb.bias ? jb.bias[c] : 0.f;
            float b1v = jb.bias ? jb.bias[c + 1] : 0.f;
            if (ra < n) {
                jb.C[(size_t)ra * FDIM + c]     = acc[s][0] + b0v;
                jb.C[(size_t)ra * FDIM + c + 1] = acc[s][1] + b1v;
            }
            if (rb < n) {
                jb.C[(size_t)rb * FDIM + c]     = acc[s][2] + b0v;
                jb.C[(size_t)rb * FDIM + c + 1] = acc[s][3] + b1v;
            }
        }
    }

    if (jb.al) {
        float pl0 = 0.f, pr0 = 0.f, pl1 = 0.f, pr1 = 0.f;
        #pragma unroll
        for (int s = 0; s < 10; s++) {
            int c = c0w + s * 8 + cq2;
            float w0 = s_al[c], w1 = s_al[c + 1];
            float v0 = s_ar[c], v1 = s_ar[c + 1];
            pl0 += acc[s][0] * w0 + acc[s][1] * w1;
            pr0 += acc[s][0] * v0 + acc[s][1] * v1;
            pl1 += acc[s][2] * w0 + acc[s][3] * w1;
            pr1 += acc[s][2] * v0 + acc[s][3] * v1;
        }
        #pragma unroll
        for (int o = 1; o <= 2; o <<= 1) {
            pl0 += __shfl_xor_sync(0xffffffffu, pl0, o);
            pr0 += __shfl_xor_sync(0xffffffffu, pr0, o);
            pl1 += __shfl_xor_sync(0xffffffffu, pl1, o);
            pr1 += __shfl_xor_sync(0xffffffffu, pr1, o);
        }
        if (kq == 0) {
            int ra = m0 + rl, rb = ra + 8;
            s_elr[wn][0][ra] = pl0; s_elr[wn][1][ra] = pr0;
            s_elr[wn][0][rb] = pl1; s_elr[wn][1][rb] = pr1;
        }
        __syncthreads();
        if (tid < 64) {
            int r = row0 + tid;
            if (r < n) {
                jb.el[r] = s_elr[0][0][tid] + s_elr[1][0][tid];
                jb.er[r] = s_elr[0][1][tid] + s_elr[1][1][tid];
            }
        }
    }
}

// ---------------- per-node kernels ----------------
__global__ void concat_kernel(const float* __restrict__ aft, const float* __restrict__ sta) {
    int idx = blockIdx.x * blockDim.x + threadIdx.x;
    if (idx >= NMAX * FDIM) return;
    int nd = idx / FDIM, f = idx % FDIM;
    float v = 0.0f;
    if (nd < N_NODES) v = (f < 144) ? aft[nd * 144 + f] : sta[nd * 16 + (f - 144)];
    g_X0[idx] = v;
}

// ---- batched fused edge-softmax + aggregation: one warp per node, blockIdx.y = job ----
__global__ void gather_batched(GatherBatch gbt) {
    const GatherJob jb = gbt.j[blockIdx.y];
    int gid = blockIdx.x * blockDim.x + threadIdx.x;
    int w = gid >> 5;
    int lane = threadIdx.x & 31;
    if (w >= jb.n) return;

    const int start = jb.off[w];
    const int end   = jb.off[w + 1];
    const float er_d = jb.er[w];
    const float* __restrict__ elp = jb.el;
    const int* __restrict__ ssrc = jb.ssrc;
    const float* __restrict__ Hp = jb.H;

    float mi = -INFINITY, si = 0.f;
    for (int j = start + lane; j < end; j += 32) {
        float z = elp[ssrc[j]] + er_d;
        z = (z > 0.f) ? z : 0.2f * z;
        if (z > mi) {
            si = si * expf(mi - z) + 1.0f;
            mi = z;
        } else {
            si += expf(z - mi);
        }
    }
    float mx = warp_max(mi);
    if (!isfinite(mx)) mx = 0.0f;
    float s = warp_sum(si * expf(mi - mx));
    const float inv = 1.0f / fmaxf(s, 1e-9f);

    float acc0 = 0.f, acc1 = 0.f, acc2 = 0.f, acc3 = 0.f, acc4 = 0.f;
    for (int g0 = start; g0 < end; g0 += 32) {
        int j = g0 + lane;
        int sN = 0; float wgt = 0.f;
        if (j < end) {
            sN = ssrc[j];
            float z = elp[sN] + er_d;
            z = (z > 0.f) ? z : 0.2f * z;
            wgt = expf(z - mx) * inv;
        }
        int cnt = min(32, end - g0);
        for (int k = 0; k < cnt; k++) {
            float wk = __shfl_sync(0xffffffffu, wgt, k);
            int   sk = __shfl_sync(0xffffffffu, sN,  k);
            const float* hp = Hp + (size_t)sk * FDIM;
            acc0 += wk * hp[lane];
            acc1 += wk * hp[lane + 32];
            acc2 += wk * hp[lane + 64];
            acc3 += wk * hp[lane + 96];
            acc4 += wk * hp[lane + 128];
        }
    }

    float* od = jb.dest + (size_t)w * FDIM;
    const float* b = jb.b;
    float v;
    v = acc0 + b[lane];       od[lane]       = (v > 0.f) ? v : 0.01f * v;
    v = acc1 + b[lane + 32];  od[lane + 32]  = (v > 0.f) ? v : 0.01f * v;
    v = acc2 + b[lane + 64];  od[lane + 64]  = (v > 0.f) ? v : 0.01f * v;
    v = acc3 + b[lane + 96];  od[lane + 96]  = (v > 0.f) ? v : 0.01f * v;
    v = acc4 + b[lane + 128]; od[lane + 128] = (v > 0.f) ? v : 0.01f * v;
}

// ---------------- precompute M1 = Wq @ Wk^T, v1 = Wk @ bq ----------------
__global__ void prep_m1_kernel(const float* __restrict__ Wq, const float* __restrict__ Wk,
                               const float* __restrict__ bq) {
    int idx = blockIdx.x * blockDim.x + threadIdx.x;
    if (idx < FDIM * FDIM) {
        int f = idx / FDIM, g = idx % FDIM;
        float s = 0.f;
        #pragma unroll 8
        for (int d = 0; d < DKDIM; d++) s += Wq[f * DKDIM + d] * Wk[g * DKDIM + d];
        g_M1[idx] = s;
    }
    if (idx < FDIM) {
        float s = 0.f;
        #pragma unroll 8
        for (int d = 0; d < DKDIM; d++) s += bq[d] * Wk[idx * DKDIM + d];
        g_v1[idx] = s;
    }
}

// ---------------- final attention merge + classifier + log_softmax ----------------
__global__ void attn_kernel(const float* __restrict__ Wl, const float* __restrict__ bl,
                            float* __restrict__ out) {
    int gid = blockIdx.x * blockDim.x + threadIdx.x;
    int w = gid >> 5;
    int lane = threadIdx.x & 31;
    if (w >= N_NODES) return;

    const float* ur = g_U + (size_t)w * FDIM;
    float u[5];
    #pragma unroll
    for (int t = 0; t < 5; t++) u[t] = ur[lane + 32 * t];

    const float* Ap[5] = { g_A1 + (size_t)w * FDIM, g_A2 + (size_t)w * FDIM,
                           g_A3 + (size_t)w * FDIM, g_A4 + (size_t)w * FDIM,
                           g_Ady + (size_t)w * FDIM };
    float a[5][5];
    #pragma unroll
    for (int j = 0; j < 5; j++)
        #pragma unroll
        for (int t = 0; t < 5; t++) a[j][t] = Ap[j][lane + 32 * t];

    float logit[5];
    #pragma unroll
    for (int j = 0; j < 5; j++) {
        float p = 0.f;
        #pragma unroll
        for (int t = 0; t < 5; t++) p += u[t] * a[j][t];
        logit[j] = warp_sum(p) * 0.125f;
    }

    float mx = logit[0];
    #pragma unroll
    for (int j = 1; j < 5; j++) mx = fmaxf(mx, logit[j]);
    float aw[5], asum = 0.f;
    #pragma unroll
    for (int j = 0; j < 5; j++) { aw[j] = expf(logit[j] - mx); asum += aw[j]; }
    float inv = 1.0f / asum;

    const float* xr = g_X0 + (size_t)w * FDIM;
    float y0 = 0.f, y1 = 0.f;
    #pragma unroll
    for (int t = 0; t < 5; t++) {
        int f = lane + 32 * t;
        float mf = 0.f;
        #pragma unroll
        for (int j = 0; j < 5; j++) mf += aw[j] * a[j][t];
        mf *= inv;
        float xv = xr[f];
        y0 += xv * Wl[2 * f]     + mf * Wl[2 * (160 + f)];
        y1 += xv * Wl[2 * f + 1] + mf * Wl[2 * (160 + f) + 1];
    }
    y0 = warp_sum(y0);
    y1 = warp_sum(y1);
    if (lane == 0) {
        y0 += bl[0]; y1 += bl[1];
        float m2 = fmaxf(y0, y1);
        float lz = m2 + logf(expf(y0 - m2) + expf(y1 - m2));
        out[2 * w]     = y0 - lz;
        out[2 * w + 1] = y1 - lz;
    }
}

// ---------------- host orchestration ----------------
static inline int cdiv(int a, int b) { return (a + b - 1) / b; }

extern "C" void kernel_launch(void* const* d_in, const int* in_sizes, int n_in,
                              void* d_out, int out_size) {
    bool sigOrder = (in_sizes[2] == 7 * FDIM * FDIM);
    int wbase = sigOrder ? 2 : 16;
    int ebase = sigOrder ? 12 : 2;

    const float* aft   = (const float*)d_in[0];
    const float* sta   = (const float*)d_in[1];
    const float* gat_W = (const float*)d_in[wbase + 0];
    const float* gat_al= (const float*)d_in[wbase + 1];
    const float* gat_ar= (const float*)d_in[wbase + 2];
    const float* gat_b = (const float*)d_in[wbase + 3];
    const float* Wq    = (const float*)d_in[wbase + 4];
    const float* bq    = (const float*)d_in[wbase + 5];
    const float* Wk    = (const float*)d_in[wbase + 6];
    const float* Wl    = (const float*)d_in[wbase + 8];
    const float* bl    = (const float*)d_in[wbase + 9];
    const int* e[14];
    for (int i = 0; i < 14; i++) e[i] = (const int*)d_in[ebase + i];

    void *pX0, *pHb, *pT3, *pT5, *pA1, *pA2, *pA3, *pA4, *pAdy, *pU, *pM1, *pV1,
         *pElB, *pErB, *pOff, *pSrc;
    cudaGetSymbolAddress(&pX0, g_X0);
    cudaGetSymbolAddress(&pHb, g_Hb);
    cudaGetSymbolAddress(&pT3, g_T3);
    cudaGetSymbolAddress(&pT5, g_T5);
    cudaGetSymbolAddress(&pA1, g_A1);
    cudaGetSymbolAddress(&pA2, g_A2);
    cudaGetSymbolAddress(&pA3, g_A3);
    cudaGetSymbolAddress(&pA4, g_A4);
    cudaGetSymbolAddress(&pAdy,g_Ady);
    cudaGetSymbolAddress(&pU,  g_U);
    cudaGetSymbolAddress(&pM1, g_M1);
    cudaGetSymbolAddress(&pV1, g_v1);
    cudaGetSymbolAddress(&pElB,g_elB);
    cudaGetSymbolAddress(&pErB,g_erB);
    cudaGetSymbolAddress(&pOff,g_offB);
    cudaGetSymbolAddress(&pSrc,g_ssrcB);

    float* X0  = (float*)pX0;
    float* T3  = (float*)pT3;
    float* T5  = (float*)pT5;
    float* A1  = (float*)pA1;
    float* A2  = (float*)pA2;
    float* A3  = (float*)pA3;
    float* A4  = (float*)pA4;
    float* Ady = (float*)pAdy;
    float* Ub  = (float*)pU;
    float* M1  = (float*)pM1;
    float* V1  = (float*)pV1;
    auto Hbuf = [&](int i) { return (float*)pHb + (size_t)i * NMAX * FDIM; };
    auto ElB  = [&](int i) { return (float*)pElB + (size_t)i * NMAX; };
    auto ErB  = [&](int i) { return (float*)pErB + (size_t)i * NMAX; };
    auto Off  = [&](int g) { return (int*)pOff + (size_t)g * OFFSTR; };
    auto Ssrc = [&](int g) { return (int*)pSrc + (size_t)g * NEDGE; };

    const int TPB = 256;
    const int GX = cdiv(NMAX, 64);
    const int GW = cdiv(NMAX * 32, TPB);

    EdgePtrs ep;
    for (int g = 0; g < NGRAPH; g++) { ep.src[g] = e[2 * g]; ep.dst[g] = e[2 * g + 1]; }

    int nL[7] = { N_NODES, N_NODES, N_NODES, N_NODES + 2, N_NODES + 2,
                  N_NODES + 20, N_NODES + 20 };

    batched_zero_kernel<<<cdiv(NGRAPH * NMAX / 4, TPB), TPB>>>();
    batched_hist_kernel<<<cdiv(NGRAPH * NEDGE, TPB), TPB>>>(ep);
    concat_kernel<<<cdiv(NMAX * FDIM, TPB), TPB>>>(aft, sta);

    // ---- launch 3 (ncu target): batched GEMM A — layers {0,1,2,3,5} from X0 ----
    GemmBatch ga;
    int laA[5] = { 0, 1, 2, 3, 5 };
    for (int k = 0; k < 5; k++) {
        int wi = laA[k];
        ga.j[k] = { X0, gat_W + (size_t)wi * FDIM * FDIM, nullptr,
                    gat_al + wi * FDIM, gat_ar + wi * FDIM,
                    Hbuf(k), ElB(k), ErB(k), nL[wi] };
    }
    gemm_tc_batched<<<dim3(GX, 5), TPB>>>(ga);

    prep_m1_kernel<<<cdiv(FDIM * FDIM, TPB), TPB>>>(Wq, Wk, bq);
    batched_scan_kernel<<<NGRAPH, 1024>>>();
    batched_fill_kernel<<<cdiv(NGRAPH * NEDGE, TPB), TPB>>>(ep);

    GatherBatch gta;
    float* destA[5] = { Ady, A1, A2, T3, T5 };
    for (int k = 0; k < 5; k++) {
        int wi = laA[k];
        gta.j[k] = { gat_b + wi * FDIM, Hbuf(k), destA[k],
                     ElB(k), ErB(k), Off(wi), Ssrc(wi), nL[wi] };
    }
    gather_batched<<<dim3(GW, 5), TPB>>>(gta);

    GemmBatch gbB;
    gbB.j[0] = { T3, gat_W + (size_t)4 * FDIM * FDIM, nullptr,
                 gat_al + 4 * FDIM, gat_ar + 4 * FDIM,
                 Hbuf(0), ElB(0), ErB(0), nL[4] };
    gbB.j[1] = { T5, gat_W + (size_t)6 * FDIM * FDIM, nullptr,
                 gat_al + 6 * FDIM, gat_ar + 6 * FDIM,
                 Hbuf(1), ElB(1), ErB(1), nL[6] };
    gbB.j[2] = { X0, M1, V1, nullptr, nullptr, Ub, nullptr, nullptr, N_NODES };
    gbB.j[3] = gbB.j[2];
    gbB.j[4] = gbB.j[2];
    gemm_tc_batched<<<dim3(GX, 3), TPB>>>(gbB);

    GatherBatch gtb;
    gtb.j[0] = { gat_b + 4 * FDIM, Hbuf(0), A3, ElB(0), ErB(0), Off(4), Ssrc(4), nL[4] };
    gtb.j[1] = { gat_b + 6 * FDIM, Hbuf(1), A4, ElB(1), ErB(1), Off(6), Ssrc(6), nL[6] };
    gtb.j[2] = gtb.j[0];
    gtb.j[3] = gtb.j[0];
    gtb.j[4] = gtb.j[0];
    gather_batched<<<dim3(GW, 2), TPB>>>(gtb);

    attn_kernel<<<cdiv(N_NODES * 32, TPB), TPB>>>(Wl, bl, (float*)d_out);
    (void)n_in; (void)out_size;
}